// round 11
// baseline (speedup 1.0000x reference)
#include <cuda_runtime.h>
#include <cuda_bf16.h>

// Piecewise-linear log-sigmoid approximation (uniform breakpoints), v9.
//
// 12x-unrolled grid-stride loop, all 12 LDG.128 batched up front
// (__launch_bounds__(256,4) -> <=64 regs so all loads stay live; 32 warps/SM
// x 6 KB = 192 KB in-flight read bytes per SM). Multi-wave grid (4 waves at
// 4 CTAs/SM) so CLC rebalances CTAs across fast/slow SMs.
//
// Index-space formulation (no branches): u = (v-x0)/h,
//   e = clamp(floor(u), -1, 64) + 1   (0..65)
//   out = Y[e] + (u - uf) * D[e]
// Guard entries: e=0 -> {x0-h, h} (exact identity for v < x0),
// e=65 -> {0,0} (zero for v >= xK).
// LUT: float2 {y, dy} replicated 32x, one column per lane -> conflict-free.

#define NSEG  64
#define NBRK  65
#define NTAB  66          // entries for idx = -1 .. 64
#define UNROLL 12

__global__ __launch_bounds__(256, 4)
void logsig_pwl_kernel(const float* __restrict__ vals,
                       const float* __restrict__ x,
                       const float* __restrict__ y,
                       float* __restrict__ out,
                       int n)
{
    __shared__ float2 tab[NTAB * 32];   // [entry][lane] {y, dy}
    __shared__ float  sc[2];            // x0, xK

    const int t = threadIdx.x;

    {
        const float x0 = x[0];
        const float xK = x[NBRK - 1];
        const float h  = (xK - x0) * (1.0f / NSEG);
        for (int j = t; j < NTAB * 32; j += blockDim.x) {
            int e = j >> 5;               // 0..65
            float2 ts;
            if (e == 0)            { ts.x = x0 - h; ts.y = h;    }
            else if (e == NTAB-1)  { ts.x = 0.0f;   ts.y = 0.0f; }
            else                   { ts.x = y[e-1]; ts.y = y[e] - y[e-1]; }
            tab[j] = ts;
        }
        if (t == 0) { sc[0] = x0; sc[1] = xK; }
    }
    __syncthreads();

    const float x0    = sc[0];
    const float xK    = sc[1];
    const float inv_h = (float)NSEG / (xK - x0);
    const float off   = -x0 * inv_h;          // u = v*inv_h + off

    const float2* __restrict__ mytab = tab + (t & 31);

    const int n4 = n >> 2;
    const float4* __restrict__ v4 = (const float4*)vals;
    float4* __restrict__ o4 = (float4*)out;

    const int tid    = blockIdx.x * blockDim.x + t;
    const int stride = gridDim.x * blockDim.x;

    #define INTERP(V, O) do {                                           \
        float u  = fmaf((V), inv_h, off);                               \
        float uf = floorf(u);                                           \
        uf = fmaxf(-1.0f, fminf(uf, 64.0f));                            \
        float fr = u - uf;             /* unclamped: extends guards */  \
        int   e  = ((int)uf + 1) << 5; /* entry * 32 */                 \
        float2 ts = mytab[e];                                           \
        (O) = fmaf(fr, ts.y, ts.x);                                     \
    } while (0)

    #define DO4(A)                                                      \
        INTERP((A).x, (A).x); INTERP((A).y, (A).y);                     \
        INTERP((A).z, (A).z); INTERP((A).w, (A).w);

    int i = tid;
    // 12x unrolled main loop: all 12 LDG.128 issued before any use
    for (; i + (UNROLL - 1) * stride < n4; i += UNROLL * stride) {
        float4 a[UNROLL];
        #pragma unroll
        for (int k = 0; k < UNROLL; k++)
            a[k] = __ldcs(&v4[i + k * stride]);
        #pragma unroll
        for (int k = 0; k < UNROLL; k++) {
            DO4(a[k]);
        }
        #pragma unroll
        for (int k = 0; k < UNROLL; k++)
            __stcs(&o4[i + k * stride], a[k]);
    }
    for (; i < n4; i += stride) {
        float4 a = __ldcs(&v4[i]);
        DO4(a);
        __stcs(&o4[i], a);
    }

    // scalar tail (n % 4 != 0 -- not hit for this shape, kept for safety)
    for (int j = (n4 << 2) + tid; j < n; j += stride) {
        float v = vals[j], o;
        INTERP(v, o);
        out[j] = o;
    }
    #undef DO4
    #undef INTERP
}

extern "C" void kernel_launch(void* const* d_in, const int* in_sizes, int n_in,
                              void* d_out, int out_size)
{
    const float* vals = (const float*)d_in[0];
    const float* x    = (const float*)d_in[1];
    const float* y    = (const float*)d_in[2];
    float* out        = (float*)d_out;
    int n = in_sizes[0];

    // 4 waves at 4 CTAs/SM (64-reg build): 148 * 4 * 4 = 2368 blocks
    int blocks = 2368;
    logsig_pwl_kernel<<<blocks, 256>>>(vals, x, y, out, n);
}

// round 12
// speedup vs baseline: 1.0104x; 1.0104x over previous
#include <cuda_runtime.h>
#include <cuda_bf16.h>

// Piecewise-linear log-sigmoid approximation (uniform breakpoints), v10.
//
// R10 body (8x-unrolled grid-stride, all 8 LDG.128 batched up front, 48 regs
// via __launch_bounds__(256,5), conflict-free per-lane float2 LUT), with a
// finer-grained multi-wave grid: 5920 blocks (~8 waves at 5 CTAs/SM) so the
// CLC work queue rebalances CTAs across fast/slow SMs with a smaller
// straggler quantum.
//
// Index-space formulation (no branches): u = (v-x0)/h,
//   e = clamp(floor(u), -1, 64) + 1   (0..65)
//   out = Y[e] + (u - uf) * D[e]
// Guard entries: e=0 -> {x0-h, h} (exact identity for v < x0),
// e=65 -> {0,0} (zero for v >= xK).

#define NSEG  64
#define NBRK  65
#define NTAB  66          // entries for idx = -1 .. 64

__global__ __launch_bounds__(256, 5)
void logsig_pwl_kernel(const float* __restrict__ vals,
                       const float* __restrict__ x,
                       const float* __restrict__ y,
                       float* __restrict__ out,
                       int n)
{
    __shared__ float2 tab[NTAB * 32];   // [entry][lane] {y, dy}
    __shared__ float  sc[2];            // x0, xK

    const int t = threadIdx.x;

    {
        const float x0 = x[0];
        const float xK = x[NBRK - 1];
        const float h  = (xK - x0) * (1.0f / NSEG);
        for (int j = t; j < NTAB * 32; j += blockDim.x) {
            int e = j >> 5;               // 0..65
            float2 ts;
            if (e == 0)            { ts.x = x0 - h; ts.y = h;    }
            else if (e == NTAB-1)  { ts.x = 0.0f;   ts.y = 0.0f; }
            else                   { ts.x = y[e-1]; ts.y = y[e] - y[e-1]; }
            tab[j] = ts;
        }
        if (t == 0) { sc[0] = x0; sc[1] = xK; }
    }
    __syncthreads();

    const float x0    = sc[0];
    const float xK    = sc[1];
    const float inv_h = (float)NSEG / (xK - x0);
    const float off   = -x0 * inv_h;          // u = v*inv_h + off

    const float2* __restrict__ mytab = tab + (t & 31);

    const int n4 = n >> 2;
    const float4* __restrict__ v4 = (const float4*)vals;
    float4* __restrict__ o4 = (float4*)out;

    const int tid    = blockIdx.x * blockDim.x + t;
    const int stride = gridDim.x * blockDim.x;

    #define INTERP(V, O) do {                                           \
        float u  = fmaf((V), inv_h, off);                               \
        float uf = floorf(u);                                           \
        uf = fmaxf(-1.0f, fminf(uf, 64.0f));                            \
        float fr = u - uf;             /* unclamped: extends guards */  \
        int   e  = ((int)uf + 1) << 5; /* entry * 32 */                 \
        float2 ts = mytab[e];                                           \
        (O) = fmaf(fr, ts.y, ts.x);                                     \
    } while (0)

    #define DO4(A, OA)                                                  \
        INTERP((A).x, (OA).x); INTERP((A).y, (OA).y);                   \
        INTERP((A).z, (OA).z); INTERP((A).w, (OA).w);

    int i = tid;
    // 8x unrolled main loop: all 8 LDG.128 issued before any use
    for (; i + 7 * stride < n4; i += 8 * stride) {
        float4 a0 = __ldcs(&v4[i]);
        float4 a1 = __ldcs(&v4[i +     stride]);
        float4 a2 = __ldcs(&v4[i + 2 * stride]);
        float4 a3 = __ldcs(&v4[i + 3 * stride]);
        float4 a4 = __ldcs(&v4[i + 4 * stride]);
        float4 a5 = __ldcs(&v4[i + 5 * stride]);
        float4 a6 = __ldcs(&v4[i + 6 * stride]);
        float4 a7 = __ldcs(&v4[i + 7 * stride]);
        float4 o0, o1, o2, o3, o4v, o5, o6, o7;
        DO4(a0, o0); DO4(a1, o1); DO4(a2, o2); DO4(a3, o3);
        DO4(a4, o4v); DO4(a5, o5); DO4(a6, o6); DO4(a7, o7);
        __stcs(&o4[i],              o0);
        __stcs(&o4[i +     stride], o1);
        __stcs(&o4[i + 2 * stride], o2);
        __stcs(&o4[i + 3 * stride], o3);
        __stcs(&o4[i + 4 * stride], o4v);
        __stcs(&o4[i + 5 * stride], o5);
        __stcs(&o4[i + 6 * stride], o6);
        __stcs(&o4[i + 7 * stride], o7);
    }
    for (; i < n4; i += stride) {
        float4 a = __ldcs(&v4[i]);
        float4 oa;
        DO4(a, oa);
        __stcs(&o4[i], oa);
    }

    // scalar tail (n % 4 != 0 -- not hit for this shape, kept for safety)
    for (int j = (n4 << 2) + tid; j < n; j += stride) {
        float v = vals[j], o;
        INTERP(v, o);
        out[j] = o;
    }
    #undef DO4
    #undef INTERP
}

extern "C" void kernel_launch(void* const* d_in, const int* in_sizes, int n_in,
                              void* d_out, int out_size)
{
    const float* vals = (const float*)d_in[0];
    const float* x    = (const float*)d_in[1];
    const float* y    = (const float*)d_in[2];
    float* out        = (float*)d_out;
    int n = in_sizes[0];

    // ~8 waves at 5 CTAs/SM: finer CLC rebalancing granularity,
    // smaller straggler tail than 4 waves.
    int blocks = 5920;
    logsig_pwl_kernel<<<blocks, 256>>>(vals, x, y, out, n);
}

// round 13
// speedup vs baseline: 1.0127x; 1.0024x over previous
#include <cuda_runtime.h>
#include <cuda_bf16.h>

// Piecewise-linear log-sigmoid approximation (uniform breakpoints), v11.
//
// 8x-unrolled grid-stride loop: all 8 LDG.128 batched up front (true MLP=8,
// 48 regs via __launch_bounds__(256,5)), then compute+store interleaved per
// slot so the write stream starts draining early instead of bursting 8
// STG.128 at iteration end. Multi-wave grid (8 waves at 5 CTAs/SM) for CLC
// rebalancing across fast/slow SMs.
//
// Index-space formulation (no branches): u = (v-x0)/h,
//   e = clamp(floor(u), -1, 64) + 1   (0..65)
//   out = Y[e] + (u - uf) * D[e]
// Guard entries: e=0 -> {x0-h, h} (exact identity for v < x0),
// e=65 -> {0,0} (zero for v >= xK).
// LUT: float2 {y, dy} replicated 32x, one column per lane -> conflict-free.

#define NSEG  64
#define NBRK  65
#define NTAB  66          // entries for idx = -1 .. 64

__global__ __launch_bounds__(256, 5)
void logsig_pwl_kernel(const float* __restrict__ vals,
                       const float* __restrict__ x,
                       const float* __restrict__ y,
                       float* __restrict__ out,
                       int n)
{
    __shared__ float2 tab[NTAB * 32];   // [entry][lane] {y, dy}
    __shared__ float  sc[2];            // x0, xK

    const int t = threadIdx.x;

    {
        const float x0 = x[0];
        const float xK = x[NBRK - 1];
        const float h  = (xK - x0) * (1.0f / NSEG);
        for (int j = t; j < NTAB * 32; j += blockDim.x) {
            int e = j >> 5;               // 0..65
            float2 ts;
            if (e == 0)            { ts.x = x0 - h; ts.y = h;    }
            else if (e == NTAB-1)  { ts.x = 0.0f;   ts.y = 0.0f; }
            else                   { ts.x = y[e-1]; ts.y = y[e] - y[e-1]; }
            tab[j] = ts;
        }
        if (t == 0) { sc[0] = x0; sc[1] = xK; }
    }
    __syncthreads();

    const float x0    = sc[0];
    const float xK    = sc[1];
    const float inv_h = (float)NSEG / (xK - x0);
    const float off   = -x0 * inv_h;          // u = v*inv_h + off

    const float2* __restrict__ mytab = tab + (t & 31);

    const int n4 = n >> 2;
    const float4* __restrict__ v4 = (const float4*)vals;
    float4* __restrict__ o4 = (float4*)out;

    const int tid    = blockIdx.x * blockDim.x + t;
    const int stride = gridDim.x * blockDim.x;

    #define INTERP(V, O) do {                                           \
        float u  = fmaf((V), inv_h, off);                               \
        float uf = floorf(u);                                           \
        uf = fmaxf(-1.0f, fminf(uf, 64.0f));                            \
        float fr = u - uf;             /* unclamped: extends guards */  \
        int   e  = ((int)uf + 1) << 5; /* entry * 32 */                 \
        float2 ts = mytab[e];                                           \
        (O) = fmaf(fr, ts.y, ts.x);                                     \
    } while (0)

    // compute 4 lanes of one float4 in place, then store it immediately
    #define DOSTORE(A, PTR) do {                                        \
        INTERP((A).x, (A).x); INTERP((A).y, (A).y);                     \
        INTERP((A).z, (A).z); INTERP((A).w, (A).w);                     \
        __stcs((PTR), (A));                                             \
    } while (0)

    int i = tid;
    // 8x unrolled: all 8 LDG.128 issued before any use; compute+store
    // interleaved per slot so writes drain while later slots compute.
    for (; i + 7 * stride < n4; i += 8 * stride) {
        float4 a0 = __ldcs(&v4[i]);
        float4 a1 = __ldcs(&v4[i +     stride]);
        float4 a2 = __ldcs(&v4[i + 2 * stride]);
        float4 a3 = __ldcs(&v4[i + 3 * stride]);
        float4 a4 = __ldcs(&v4[i + 4 * stride]);
        float4 a5 = __ldcs(&v4[i + 5 * stride]);
        float4 a6 = __ldcs(&v4[i + 6 * stride]);
        float4 a7 = __ldcs(&v4[i + 7 * stride]);
        DOSTORE(a0, &o4[i]);
        DOSTORE(a1, &o4[i +     stride]);
        DOSTORE(a2, &o4[i + 2 * stride]);
        DOSTORE(a3, &o4[i + 3 * stride]);
        DOSTORE(a4, &o4[i + 4 * stride]);
        DOSTORE(a5, &o4[i + 5 * stride]);
        DOSTORE(a6, &o4[i + 6 * stride]);
        DOSTORE(a7, &o4[i + 7 * stride]);
    }
    for (; i < n4; i += stride) {
        float4 a = __ldcs(&v4[i]);
        DOSTORE(a, &o4[i]);
    }

    // scalar tail (n % 4 != 0 -- not hit for this shape, kept for safety)
    for (int j = (n4 << 2) + tid; j < n; j += stride) {
        float v = vals[j], o;
        INTERP(v, o);
        out[j] = o;
    }
    #undef DOSTORE
    #undef INTERP
}

extern "C" void kernel_launch(void* const* d_in, const int* in_sizes, int n_in,
                              void* d_out, int out_size)
{
    const float* vals = (const float*)d_in[0];
    const float* x    = (const float*)d_in[1];
    const float* y    = (const float*)d_in[2];
    float* out        = (float*)d_out;
    int n = in_sizes[0];

    // ~8 waves at 5 CTAs/SM (48-reg build): CLC rebalances CTAs across SMs
    int blocks = 5920;
    logsig_pwl_kernel<<<blocks, 256>>>(vals, x, y, out, n);
}

// round 14
// speedup vs baseline: 1.0396x; 1.0265x over previous
#include <cuda_runtime.h>
#include <cuda_bf16.h>

// Piecewise-linear log-sigmoid approximation (uniform breakpoints), v12.
//
// Warp-blocked addressing: each warp processes one CONTIGUOUS 4 KB block per
// iteration (8 slots of 512 B, each LDG.128/STG.128 fully coalesced), instead
// of 8 slots scattered 24 MB apart. Reads and writes become long sequential
// bursts per warp -> better HBM row-buffer locality at the controller.
//
// Kept from best kernel: 8 LDG.128 batched up front (MLP=8, 48 regs via
// __launch_bounds__(256,5)), conflict-free per-lane float2 LUT, streaming
// ld/st hints, multi-wave grid (8 waves at 5 CTAs/SM) for CLC rebalancing.
//
// Index-space formulation (no branches): u = (v-x0)/h,
//   e = clamp(floor(u), -1, 64) + 1   (0..65)
//   out = Y[e] + (u - uf) * D[e]
// Guard entries: e=0 -> {x0-h, h} (exact identity for v < x0),
// e=65 -> {0,0} (zero for v >= xK).

#define NSEG  64
#define NBRK  65
#define NTAB  66          // entries for idx = -1 .. 64
#define UNROLL 8

__global__ __launch_bounds__(256, 5)
void logsig_pwl_kernel(const float* __restrict__ vals,
                       const float* __restrict__ x,
                       const float* __restrict__ y,
                       float* __restrict__ out,
                       int n)
{
    __shared__ float2 tab[NTAB * 32];   // [entry][lane] {y, dy}
    __shared__ float  sc[2];            // x0, xK

    const int t = threadIdx.x;

    {
        const float x0 = x[0];
        const float xK = x[NBRK - 1];
        const float h  = (xK - x0) * (1.0f / NSEG);
        for (int j = t; j < NTAB * 32; j += blockDim.x) {
            int e = j >> 5;               // 0..65
            float2 ts;
            if (e == 0)            { ts.x = x0 - h; ts.y = h;    }
            else if (e == NTAB-1)  { ts.x = 0.0f;   ts.y = 0.0f; }
            else                   { ts.x = y[e-1]; ts.y = y[e] - y[e-1]; }
            tab[j] = ts;
        }
        if (t == 0) { sc[0] = x0; sc[1] = xK; }
    }
    __syncthreads();

    const float x0    = sc[0];
    const float xK    = sc[1];
    const float inv_h = (float)NSEG / (xK - x0);
    const float off   = -x0 * inv_h;          // u = v*inv_h + off

    const int lane = t & 31;
    const float2* __restrict__ mytab = tab + lane;

    const int n4 = n >> 2;
    const float4* __restrict__ v4 = (const float4*)vals;
    float4* __restrict__ o4 = (float4*)out;

    // warp-blocked indexing: global warp id, each warp owns contiguous
    // UNROLL*32 float4s (4 KB) per iteration.
    const int gwarp   = (blockIdx.x * blockDim.x + t) >> 5;
    const int nwarps  = (gridDim.x * blockDim.x) >> 5;
    const int wstride = nwarps * (UNROLL * 32);   // float4s per full pass

    #define INTERP(V, O) do {                                           \
        float u  = fmaf((V), inv_h, off);                               \
        float uf = floorf(u);                                           \
        uf = fmaxf(-1.0f, fminf(uf, 64.0f));                            \
        float fr = u - uf;             /* unclamped: extends guards */  \
        int   e  = ((int)uf + 1) << 5; /* entry * 32 */                 \
        float2 ts = mytab[e];                                           \
        (O) = fmaf(fr, ts.y, ts.x);                                     \
    } while (0)

    #define DO4(A, OA)                                                  \
        INTERP((A).x, (OA).x); INTERP((A).y, (OA).y);                   \
        INTERP((A).z, (OA).z); INTERP((A).w, (OA).w);

    int base = gwarp * (UNROLL * 32) + lane;
    // main loop: warp covers [base .. base+8*32) contiguous float4s
    for (; base + (UNROLL - 1) * 32 < n4; base += wstride) {
        float4 a0 = __ldcs(&v4[base]);
        float4 a1 = __ldcs(&v4[base + 1 * 32]);
        float4 a2 = __ldcs(&v4[base + 2 * 32]);
        float4 a3 = __ldcs(&v4[base + 3 * 32]);
        float4 a4 = __ldcs(&v4[base + 4 * 32]);
        float4 a5 = __ldcs(&v4[base + 5 * 32]);
        float4 a6 = __ldcs(&v4[base + 6 * 32]);
        float4 a7 = __ldcs(&v4[base + 7 * 32]);
        float4 o0, o1, o2, o3, o4v, o5, o6, o7;
        DO4(a0, o0); DO4(a1, o1); DO4(a2, o2); DO4(a3, o3);
        DO4(a4, o4v); DO4(a5, o5); DO4(a6, o6); DO4(a7, o7);
        __stcs(&o4[base],          o0);
        __stcs(&o4[base + 1 * 32], o1);
        __stcs(&o4[base + 2 * 32], o2);
        __stcs(&o4[base + 3 * 32], o3);
        __stcs(&o4[base + 4 * 32], o4v);
        __stcs(&o4[base + 5 * 32], o5);
        __stcs(&o4[base + 6 * 32], o6);
        __stcs(&o4[base + 7 * 32], o7);
    }
    // remainder float4s for this warp's final (partial) block
    for (; base < n4; base += 32) {
        float4 a = __ldcs(&v4[base]);
        float4 oa;
        DO4(a, oa);
        __stcs(&o4[base], oa);
    }

    // scalar tail (n % 4 != 0 -- not hit for this shape, kept for safety)
    for (int j = (n4 << 2) + blockIdx.x * blockDim.x + t; j < n;
         j += gridDim.x * blockDim.x) {
        float v = vals[j], o;
        INTERP(v, o);
        out[j] = o;
    }
    #undef DO4
    #undef INTERP
}

extern "C" void kernel_launch(void* const* d_in, const int* in_sizes, int n_in,
                              void* d_out, int out_size)
{
    const float* vals = (const float*)d_in[0];
    const float* x    = (const float*)d_in[1];
    const float* y    = (const float*)d_in[2];
    float* out        = (float*)d_out;
    int n = in_sizes[0];

    // ~8 waves at 5 CTAs/SM (48-reg build)
    int blocks = 5920;
    logsig_pwl_kernel<<<blocks, 256>>>(vals, x, y, out, n);
}